// round 6
// baseline (speedup 1.0000x reference)
#include <cuda_runtime.h>
#include <math.h>

// Problem constants
#define NB      16
#define HW      262144           // 512*512
#define KRANK   104856u          // int(512*512*0.4 - 1)
#define NBINS   16384            // value-space bins: bin = min(16383, int(gray*16384))
#define CAP     2048             // per-batch boundary-pixel capacity (expected ~24)
#define P3BLOCKS 2048
#define TOTAL_ELEMS (16.0*3.0*512.0*512.0)

// Device scratch (.bss zero-init; finalize re-zeroes hist + counters per replay)
__device__ unsigned int g_hist[NB * NBINS];       // 1 MB
__device__ unsigned int g_bin[NB];
__device__ unsigned int g_rank[NB];
__device__ unsigned int g_bnd_cnt[NB];
__device__ float        g_bnd_g[NB * CAP];
__device__ float        g_bnd_d[NB * CAP];
__device__ float        g_partial[P3BLOCKS];

__device__ __forceinline__ unsigned int gray_bin(float g) {
    int v = (int)(g * 16384.0f);
    if (v > NBINS - 1) v = NBINS - 1;
    if (v < 0) v = 0;
    return (unsigned int)v;
}

// ---------------------------------------------------------------------------
// K1: value-space histogram of gray = (c0+c1+c2)/3.  NO gray store.
// 1024 blocks (64/batch) x 256 thr; 16 px/thread.
// ---------------------------------------------------------------------------
__global__ void pass1_hist(const float* __restrict__ yp) {
    int b = blockIdx.x >> 6;
    int r = blockIdx.x & 63;
    int t = threadIdx.x;

    const float4* c0 = (const float4*)yp + (size_t)b * 3 * (HW/4) + 0 * (HW/4) + r * 1024;
    const float4* c1 = (const float4*)yp + (size_t)b * 3 * (HW/4) + 1 * (HW/4) + r * 1024;
    const float4* c2 = (const float4*)yp + (size_t)b * 3 * (HW/4) + 2 * (HW/4) + r * 1024;
    unsigned int* h = g_hist + (size_t)b * NBINS;

    #pragma unroll
    for (int q = 0; q < 4; q++) {
        int o = t + q * 256;
        float4 a = c0[o], x = c1[o], y = c2[o];
        float g0 = (a.x + x.x + y.x) / 3.0f;
        float g1 = (a.y + x.y + y.y) / 3.0f;
        float g2 = (a.z + x.z + y.z) / 3.0f;
        float g3 = (a.w + x.w + y.w) / 3.0f;
        atomicAdd(&h[gray_bin(g0)], 1u);
        atomicAdd(&h[gray_bin(g1)], 1u);
        atomicAdd(&h[gray_bin(g2)], 1u);
        atomicAdd(&h[gray_bin(g3)], 1u);
    }
}

// ---------------------------------------------------------------------------
// K2: find value-bin containing rank KRANK + within-bin rank.  16 blocks x 256.
// ---------------------------------------------------------------------------
__global__ void select1() {
    int b = blockIdx.x;
    const uint4* h4 = (const uint4*)(g_hist + (size_t)b * NBINS);  // 4096 uint4
    __shared__ unsigned int partial[64];
    __shared__ unsigned int fine[256];
    __shared__ int s_chunk;
    __shared__ unsigned int s_rem;

    int warp = threadIdx.x >> 5;
    int lane = threadIdx.x & 31;

    #pragma unroll
    for (int it = 0; it < 8; it++) {
        int c = warp + 8 * it;
        uint4 v1 = h4[c * 64 + lane];
        uint4 v2 = h4[c * 64 + 32 + lane];
        unsigned int s = v1.x+v1.y+v1.z+v1.w + v2.x+v2.y+v2.z+v2.w;
        #pragma unroll
        for (int o = 16; o > 0; o >>= 1) s += __shfl_down_sync(0xFFFFFFFFu, s, o);
        if (lane == 0) partial[c] = s;
    }
    __syncthreads();

    if (threadIdx.x == 0) {
        unsigned int k = KRANK, cum = 0;
        int cb = 63;
        for (int j = 0; j < 64; j++) {
            if (k < cum + partial[j]) { cb = j; break; }
            cum += partial[j];
        }
        s_chunk = cb; s_rem = k - cum;
    }
    __syncthreads();

    int cb = s_chunk;
    fine[threadIdx.x] = g_hist[(size_t)b * NBINS + cb * 256 + threadIdx.x];
    __syncthreads();

    if (threadIdx.x == 0) {
        unsigned int k = s_rem, cum = 0;
        int fb = 255;
        for (int i = 0; i < 256; i++) {
            if (k < cum + fine[i]) { fb = i; break; }
            cum += fine[i];
        }
        g_bin[b]  = (unsigned int)(cb * 256 + fb);
        g_rank[b] = k - cum;        // within-bin rank (0-based)
    }
}

// ---------------------------------------------------------------------------
// K3: weighted L1 with bin-level mask; boundary-bin pixels get provisional
// 0.2 weight and are appended (gray, d) for exact correction in finalize.
// 2048 blocks (128/batch) x 256 thr; 8 px/thread.
// ---------------------------------------------------------------------------
__global__ void pass3_loss(const float* __restrict__ yt,
                           const float* __restrict__ yp) {
    int b = blockIdx.x >> 7;
    int r = blockIdx.x & 127;
    int t = threadIdx.x;
    unsigned int selbin = g_bin[b];

    size_t base4 = (size_t)b * 3 * (HW/4);
    const float4* p0 = (const float4*)yp + base4 + 0*(HW/4) + r*512;
    const float4* p1 = (const float4*)yp + base4 + 1*(HW/4) + r*512;
    const float4* p2 = (const float4*)yp + base4 + 2*(HW/4) + r*512;
    const float4* q0 = (const float4*)yt + base4 + 0*(HW/4) + r*512;
    const float4* q1 = (const float4*)yt + base4 + 1*(HW/4) + r*512;
    const float4* q2 = (const float4*)yt + base4 + 2*(HW/4) + r*512;

    float s = 0.0f;
    #pragma unroll
    for (int qq = 0; qq < 2; qq++) {
        int o = t + qq * 256;
        float4 a = q0 ? p0[o] : p0[o];  // keep simple
        a = p0[o];
        float4 x = p1[o], y = p2[o];
        float4 u = q0[o], v = q1[o], w = q2[o];

        float gr[4], dd[4];
        gr[0] = (a.x + x.x + y.x) / 3.0f;
        gr[1] = (a.y + x.y + y.y) / 3.0f;
        gr[2] = (a.z + x.z + y.z) / 3.0f;
        gr[3] = (a.w + x.w + y.w) / 3.0f;
        dd[0] = fabsf(a.x-u.x) + fabsf(x.x-v.x) + fabsf(y.x-w.x);
        dd[1] = fabsf(a.y-u.y) + fabsf(x.y-v.y) + fabsf(y.y-w.y);
        dd[2] = fabsf(a.z-u.z) + fabsf(x.z-v.z) + fabsf(y.z-w.z);
        dd[3] = fabsf(a.w-u.w) + fabsf(x.w-v.w) + fabsf(y.w-w.w);

        #pragma unroll
        for (int i = 0; i < 4; i++) {
            unsigned int bn = gray_bin(gr[i]);
            float wt = (bn < selbin) ? 0.8f : 0.2f;
            if (bn == selbin) {
                unsigned int p = atomicAdd(&g_bnd_cnt[b], 1u);
                if (p < CAP) {
                    g_bnd_g[(size_t)b * CAP + p] = gr[i];
                    g_bnd_d[(size_t)b * CAP + p] = dd[i];
                }
            }
            s += wt * dd[i];
        }
    }

    #pragma unroll
    for (int o = 16; o > 0; o >>= 1)
        s += __shfl_down_sync(0xFFFFFFFFu, s, o);

    __shared__ float ws[8];
    int lane = threadIdx.x & 31;
    int warp = threadIdx.x >> 5;
    if (lane == 0) ws[warp] = s;
    __syncthreads();
    if (warp == 0) {
        float vv = (lane < 8) ? ws[lane] : 0.0f;
        #pragma unroll
        for (int o = 4; o > 0; o >>= 1)
            vv += __shfl_down_sync(0xFFFFFFFFu, vv, o);
        if (lane == 0) g_partial[blockIdx.x] = vv;
    }
}

// ---------------------------------------------------------------------------
// K4: block 0: reduce partials (double) + exact boundary corrections;
// all blocks: zero hist for next replay.  256 blocks x 256 thr.
// ---------------------------------------------------------------------------
__global__ void finalize(float* __restrict__ out) {
    int t = threadIdx.x;
    int zi = blockIdx.x * 256 + t;                 // 65536 uint4 = 1 MB hist
    ((uint4*)g_hist)[zi] = make_uint4(0u, 0u, 0u, 0u);

    if (blockIdx.x != 0) return;

    double s = 0.0;
    #pragma unroll
    for (int i = 0; i < P3BLOCKS / 256; i++)
        s += (double)g_partial[t + i * 256];

    __shared__ float s_g[CAP];
    __shared__ float s_d[CAP];
    __shared__ float s_kthv;
    __shared__ unsigned int s_n;

    for (int b = 0; b < NB; b++) {
        if (t == 0) {
            unsigned int n = g_bnd_cnt[b];
            s_n = (n > CAP) ? CAP : n;
        }
        __syncthreads();
        unsigned int n = s_n;
        for (unsigned int i = t; i < n; i += 256) {
            s_g[i] = g_bnd_g[(size_t)b * CAP + i];
            s_d[i] = g_bnd_d[(size_t)b * CAP + i];
        }
        __syncthreads();

        unsigned int k = g_rank[b];
        for (unsigned int i = t; i < n; i += 256) {
            float v = s_g[i];
            unsigned int cl = 0, ce = 0;
            for (unsigned int j = 0; j < n; j++) {
                float w2 = s_g[j];
                cl += (w2 < v);
                ce += (w2 == v);
            }
            if (cl <= k && k < cl + ce) s_kthv = v;   // unique value
        }
        __syncthreads();

        float kthv = s_kthv;
        for (unsigned int i = t; i < n; i += 256)
            if (s_g[i] <= kthv) s += 0.6 * (double)s_d[i];
        __syncthreads();
    }

    if (t < NB) g_bnd_cnt[t] = 0u;                 // reset for next replay

    #pragma unroll
    for (int o = 16; o > 0; o >>= 1)
        s += __shfl_down_sync(0xFFFFFFFFu, s, o);

    __shared__ double ds[8];
    int lane = t & 31;
    int warp = t >> 5;
    if (lane == 0) ds[warp] = s;
    __syncthreads();
    if (warp == 0) {
        double v = (lane < 8) ? ds[lane] : 0.0;
        #pragma unroll
        for (int o = 4; o > 0; o >>= 1)
            v += __shfl_down_sync(0xFFFFFFFFu, v, o);
        if (lane == 0) out[0] = (float)(v / TOTAL_ELEMS);
    }
}

// ---------------------------------------------------------------------------
extern "C" void kernel_launch(void* const* d_in, const int* in_sizes, int n_in,
                              void* d_out, int out_size) {
    const float* y_true = (const float*)d_in[0];
    const float* y_pred = (const float*)d_in[1];
    float* out = (float*)d_out;

    pass1_hist<<<1024, 256>>>(y_pred);
    select1<<<NB, 256>>>();
    pass3_loss<<<P3BLOCKS, 256>>>(y_true, y_pred);
    finalize<<<256, 256>>>(out);
}

// round 7
// speedup vs baseline: 1.3065x; 1.3065x over previous
#include <cuda_runtime.h>
#include <math.h>

// Problem constants
#define NB      16
#define HW      262144           // 512*512
#define KRANK   104856u          // int(512*512*0.4 - 1)
#define NBINS   16384            // value-space bins: bin = min(16383, int(gray*16384))
#define CAP     2048             // per-batch boundary-pixel capacity (expected ~24)
#define P3BLOCKS 1024
#define TOTAL_ELEMS (16.0*3.0*512.0*512.0)

// Device scratch (.bss zero-init; re-zeroed each replay by correct/finalize)
__device__ unsigned int g_hist[NB * NBINS];       // 1 MB
__device__ unsigned int g_bin[NB];
__device__ unsigned int g_rank[NB];
__device__ unsigned int g_bnd_cnt[NB];
__device__ float        g_bnd_g[NB * CAP];
__device__ float        g_bnd_d[NB * CAP];
__device__ double       g_corr[NB];
__device__ float        g_partial[P3BLOCKS];

__device__ __forceinline__ unsigned int gray_bin(float g) {
    int v = (int)(g * 16384.0f);
    if (v > NBINS - 1) v = NBINS - 1;
    if (v < 0) v = 0;
    return (unsigned int)v;
}

// ---------------------------------------------------------------------------
// K1: value-space histogram of gray = (c0+c1+c2)/3.  NO gray store.
// 1024 blocks (64/batch) x 256 thr; 16 px/thread.
// ---------------------------------------------------------------------------
__global__ void pass1_hist(const float* __restrict__ yp) {
    int b = blockIdx.x >> 6;
    int r = blockIdx.x & 63;
    int t = threadIdx.x;

    const float4* c0 = (const float4*)yp + (size_t)b * 3 * (HW/4) + 0 * (HW/4) + r * 1024;
    const float4* c1 = (const float4*)yp + (size_t)b * 3 * (HW/4) + 1 * (HW/4) + r * 1024;
    const float4* c2 = (const float4*)yp + (size_t)b * 3 * (HW/4) + 2 * (HW/4) + r * 1024;
    unsigned int* h = g_hist + (size_t)b * NBINS;

    #pragma unroll
    for (int q = 0; q < 4; q++) {
        int o = t + q * 256;
        float4 a = c0[o], x = c1[o], y = c2[o];
        float g0 = (a.x + x.x + y.x) / 3.0f;
        float g1 = (a.y + x.y + y.y) / 3.0f;
        float g2 = (a.z + x.z + y.z) / 3.0f;
        float g3 = (a.w + x.w + y.w) / 3.0f;
        atomicAdd(&h[gray_bin(g0)], 1u);
        atomicAdd(&h[gray_bin(g1)], 1u);
        atomicAdd(&h[gray_bin(g2)], 1u);
        atomicAdd(&h[gray_bin(g3)], 1u);
    }
}

// ---------------------------------------------------------------------------
// K2: find value-bin containing rank KRANK + within-bin rank.  16 blocks x 256.
// ---------------------------------------------------------------------------
__global__ void select1() {
    int b = blockIdx.x;
    const uint4* h4 = (const uint4*)(g_hist + (size_t)b * NBINS);  // 4096 uint4
    __shared__ unsigned int partial[64];
    __shared__ unsigned int fine[256];
    __shared__ int s_chunk;
    __shared__ unsigned int s_rem;

    int warp = threadIdx.x >> 5;
    int lane = threadIdx.x & 31;

    #pragma unroll
    for (int it = 0; it < 8; it++) {
        int c = warp + 8 * it;
        uint4 v1 = h4[c * 64 + lane];
        uint4 v2 = h4[c * 64 + 32 + lane];
        unsigned int s = v1.x+v1.y+v1.z+v1.w + v2.x+v2.y+v2.z+v2.w;
        #pragma unroll
        for (int o = 16; o > 0; o >>= 1) s += __shfl_down_sync(0xFFFFFFFFu, s, o);
        if (lane == 0) partial[c] = s;
    }
    __syncthreads();

    if (threadIdx.x == 0) {
        unsigned int k = KRANK, cum = 0;
        int cb = 63;
        for (int j = 0; j < 64; j++) {
            if (k < cum + partial[j]) { cb = j; break; }
            cum += partial[j];
        }
        s_chunk = cb; s_rem = k - cum;
    }
    __syncthreads();

    int cb = s_chunk;
    fine[threadIdx.x] = g_hist[(size_t)b * NBINS + cb * 256 + threadIdx.x];
    __syncthreads();

    if (threadIdx.x == 0) {
        unsigned int k = s_rem, cum = 0;
        int fb = 255;
        for (int i = 0; i < 256; i++) {
            if (k < cum + fine[i]) { fb = i; break; }
            cum += fine[i];
        }
        g_bin[b]  = (unsigned int)(cb * 256 + fb);
        g_rank[b] = k - cum;        // within-bin rank (0-based)
    }
}

// ---------------------------------------------------------------------------
// K3: weighted L1 with bin-level mask; boundary-bin pixels get provisional
// 0.2 weight and are appended (gray, d) for exact correction later.
// 1024 blocks (64/batch) x 256 thr; 16 px/thread.
// ---------------------------------------------------------------------------
__global__ void pass3_loss(const float* __restrict__ yt,
                           const float* __restrict__ yp) {
    int b = blockIdx.x >> 6;
    int r = blockIdx.x & 63;
    int t = threadIdx.x;
    unsigned int selbin = g_bin[b];

    size_t base4 = (size_t)b * 3 * (HW/4);
    const float4* p0 = (const float4*)yp + base4 + 0*(HW/4) + r*1024;
    const float4* p1 = (const float4*)yp + base4 + 1*(HW/4) + r*1024;
    const float4* p2 = (const float4*)yp + base4 + 2*(HW/4) + r*1024;
    const float4* q0 = (const float4*)yt + base4 + 0*(HW/4) + r*1024;
    const float4* q1 = (const float4*)yt + base4 + 1*(HW/4) + r*1024;
    const float4* q2 = (const float4*)yt + base4 + 2*(HW/4) + r*1024;

    float s = 0.0f;
    #pragma unroll
    for (int qq = 0; qq < 4; qq++) {
        int o = t + qq * 256;
        float4 a = p0[o], x = p1[o], y = p2[o];
        float4 u = q0[o], v = q1[o], w = q2[o];

        float gr[4], dd[4];
        gr[0] = (a.x + x.x + y.x) / 3.0f;
        gr[1] = (a.y + x.y + y.y) / 3.0f;
        gr[2] = (a.z + x.z + y.z) / 3.0f;
        gr[3] = (a.w + x.w + y.w) / 3.0f;
        dd[0] = fabsf(a.x-u.x) + fabsf(x.x-v.x) + fabsf(y.x-w.x);
        dd[1] = fabsf(a.y-u.y) + fabsf(x.y-v.y) + fabsf(y.y-w.y);
        dd[2] = fabsf(a.z-u.z) + fabsf(x.z-v.z) + fabsf(y.z-w.z);
        dd[3] = fabsf(a.w-u.w) + fabsf(x.w-v.w) + fabsf(y.w-w.w);

        #pragma unroll
        for (int i = 0; i < 4; i++) {
            unsigned int bn = gray_bin(gr[i]);
            float wt = (bn < selbin) ? 0.8f : 0.2f;
            if (bn == selbin) {
                unsigned int p = atomicAdd(&g_bnd_cnt[b], 1u);
                if (p < CAP) {
                    g_bnd_g[(size_t)b * CAP + p] = gr[i];
                    g_bnd_d[(size_t)b * CAP + p] = dd[i];
                }
            }
            s += wt * dd[i];
        }
    }

    #pragma unroll
    for (int o = 16; o > 0; o >>= 1)
        s += __shfl_down_sync(0xFFFFFFFFu, s, o);

    __shared__ float ws[8];
    int lane = threadIdx.x & 31;
    int warp = threadIdx.x >> 5;
    if (lane == 0) ws[warp] = s;
    __syncthreads();
    if (warp == 0) {
        float vv = (lane < 8) ? ws[lane] : 0.0f;
        #pragma unroll
        for (int o = 4; o > 0; o >>= 1)
            vv += __shfl_down_sync(0xFFFFFFFFu, vv, o);
        if (lane == 0) g_partial[blockIdx.x] = vv;
    }
}

// ---------------------------------------------------------------------------
// K4: per-batch exact boundary correction.  16 blocks (1/batch) x 256 thr.
// corr[b] = 0.6 * sum(d_i for boundary pixels with gray_i <= kth value).
// ---------------------------------------------------------------------------
__global__ void correct() {
    int b = blockIdx.x;
    int t = threadIdx.x;

    __shared__ float s_g[CAP];
    __shared__ float s_d[CAP];
    __shared__ float s_kthv;
    __shared__ unsigned int s_n;

    if (t == 0) {
        unsigned int n = g_bnd_cnt[b];
        s_n = (n > CAP) ? CAP : n;
        g_bnd_cnt[b] = 0u;                // reset for next replay
    }
    __syncthreads();
    unsigned int n = s_n;

    for (unsigned int i = t; i < n; i += 256) {
        s_g[i] = g_bnd_g[(size_t)b * CAP + i];
        s_d[i] = g_bnd_d[(size_t)b * CAP + i];
    }
    __syncthreads();

    unsigned int k = g_rank[b];
    for (unsigned int i = t; i < n; i += 256) {
        float v = s_g[i];
        unsigned int cl = 0, ce = 0;
        for (unsigned int j = 0; j < n; j++) {
            float w2 = s_g[j];
            cl += (w2 < v);
            ce += (w2 == v);
        }
        if (cl <= k && k < cl + ce) s_kthv = v;   // unique value; single writer
    }
    __syncthreads();

    float kthv = s_kthv;
    float c = 0.0f;
    for (unsigned int i = t; i < n; i += 256)
        if (s_g[i] <= kthv) c += s_d[i];

    #pragma unroll
    for (int o = 16; o > 0; o >>= 1)
        c += __shfl_down_sync(0xFFFFFFFFu, c, o);

    __shared__ float ws[8];
    int lane = t & 31;
    int warp = t >> 5;
    if (lane == 0) ws[warp] = c;
    __syncthreads();
    if (warp == 0) {
        float vv = (lane < 8) ? ws[lane] : 0.0f;
        #pragma unroll
        for (int o = 4; o > 0; o >>= 1)
            vv += __shfl_down_sync(0xFFFFFFFFu, vv, o);
        if (lane == 0) g_corr[b] = 0.6 * (double)vv;
    }
}

// ---------------------------------------------------------------------------
// K5: all blocks zero hist; block 0 reduces partials + corrections.
// 256 blocks x 256 thr.
// ---------------------------------------------------------------------------
__global__ void finalize(float* __restrict__ out) {
    int t = threadIdx.x;
    int zi = blockIdx.x * 256 + t;                 // 65536 uint4 = 1 MB hist
    ((uint4*)g_hist)[zi] = make_uint4(0u, 0u, 0u, 0u);

    if (blockIdx.x != 0) return;

    double s = 0.0;
    #pragma unroll
    for (int i = 0; i < P3BLOCKS / 256; i++)
        s += (double)g_partial[t + i * 256];
    if (t < NB) s += g_corr[t];

    #pragma unroll
    for (int o = 16; o > 0; o >>= 1)
        s += __shfl_down_sync(0xFFFFFFFFu, s, o);

    __shared__ double ds[8];
    int lane = t & 31;
    int warp = t >> 5;
    if (lane == 0) ds[warp] = s;
    __syncthreads();
    if (warp == 0) {
        double v = (lane < 8) ? ds[lane] : 0.0;
        #pragma unroll
        for (int o = 4; o > 0; o >>= 1)
            v += __shfl_down_sync(0xFFFFFFFFu, v, o);
        if (lane == 0) out[0] = (float)(v / TOTAL_ELEMS);
    }
}

// ---------------------------------------------------------------------------
extern "C" void kernel_launch(void* const* d_in, const int* in_sizes, int n_in,
                              void* d_out, int out_size) {
    const float* y_true = (const float*)d_in[0];
    const float* y_pred = (const float*)d_in[1];
    float* out = (float*)d_out;

    pass1_hist<<<1024, 256>>>(y_pred);
    select1<<<NB, 256>>>();
    pass3_loss<<<P3BLOCKS, 256>>>(y_true, y_pred);
    correct<<<NB, 256>>>();
    finalize<<<256, 256>>>(out);
}